// round 9
// baseline (speedup 1.0000x reference)
#include <cuda_runtime.h>
#include <cstdint>

// Problem shape (fixed by setup_inputs): B=4, N=4096, coords [B,N,3] f32, radii [B,N] f32 in [0,1).
#define BB 4
#define NN 4096
#define GDIM 16                 // 16^3 cells, cell size 4.0, origin -32 (covers +/-32 >> 4.5 sigma)
#define NCELL (GDIM * GDIM * GDIM)
#define GSZ 16                  // points per bounding group
#define NGRP (NN / GSZ)         // 256 groups per batch
#define TILE_I 128
#define NSPLIT 4
#define GPS (NGRP / NSPLIT)     // 64 groups per split
#define JS  (GPS * GSZ)         // 1024 j-points per split
#define NGROUP (BB * (NN / TILE_I))   // reduction groups (b,itile)

// Scratch (__device__ globals; no allocs allowed).
__device__ float4 g_spts[BB * NN];    // sorted (x,y,z,r)
__device__ int    g_sidx[BB * NN];    // sorted -> original global point index
__device__ float4 g_grp [BB * NGRP];  // (cx,cy,cz,(2+rg)^2)
__device__ float  g_part[(size_t)NSPLIT * BB * NN * 3];
__device__ int    g_done[NGROUP];     // zero-init; winner resets -> replay-safe

__device__ __forceinline__ int cell_of(float v) {
    int c = (int)floorf((v + 32.0f) * 0.25f);
    return min(GDIM - 1, max(0, c));
}

// ---- K1: per-batch counting sort by cell (1 block of 1024 per batch) ----
__global__ __launch_bounds__(1024)
void k_sort(const float* __restrict__ coords, const float* __restrict__ radii) {
    __shared__ int hist[NCELL];     // 16KB
    __shared__ int wsum[32];
    const int b = blockIdx.x, t = threadIdx.x;

    for (int c = t; c < NCELL; c += 1024) hist[c] = 0;
    __syncthreads();

    float4 pt[4]; int cell[4], rank[4], pidx[4];
    #pragma unroll
    for (int k = 0; k < 4; k++) {
        const int p  = k * 1024 + t;        // batch-local
        const int gp = b * NN + p;
        const float x = coords[3 * gp], y = coords[3 * gp + 1], z = coords[3 * gp + 2];
        pt[k]   = make_float4(x, y, z, radii[gp]);
        pidx[k] = gp;
        cell[k] = (cell_of(z) * GDIM + cell_of(y)) * GDIM + cell_of(x);
        rank[k] = atomicAdd(&hist[cell[k]], 1);
    }
    __syncthreads();

    // Exclusive scan of 4096 cell counts (4 cells/thread).
    const int c0 = hist[4 * t], c1 = hist[4 * t + 1], c2 = hist[4 * t + 2], c3 = hist[4 * t + 3];
    const int s  = c0 + c1 + c2 + c3;
    const int lane = t & 31, wid = t >> 5;
    int v = s;
    #pragma unroll
    for (int off = 1; off < 32; off <<= 1) {
        int u = __shfl_up_sync(0xffffffffu, v, off);
        if (lane >= off) v += u;
    }
    if (lane == 31) wsum[wid] = v;
    __syncthreads();
    if (wid == 0) {
        int w = wsum[lane];
        #pragma unroll
        for (int off = 1; off < 32; off <<= 1) {
            int u = __shfl_up_sync(0xffffffffu, w, off);
            if (lane >= off) w += u;
        }
        wsum[lane] = w;
    }
    __syncthreads();
    int pref = v - s + (wid > 0 ? wsum[wid - 1] : 0);
    __syncthreads();             // everyone read old hist? (c0..c3 already in regs) - safe to overwrite
    hist[4 * t]     = pref;
    hist[4 * t + 1] = pref + c0;
    hist[4 * t + 2] = pref + c0 + c1;
    hist[4 * t + 3] = pref + c0 + c1 + c2;
    __syncthreads();

    #pragma unroll
    for (int k = 0; k < 4; k++) {
        const int pos = hist[cell[k]] + rank[k];
        g_spts[b * NN + pos] = pt[k];
        g_sidx[b * NN + pos] = pidx[k];
    }
}

// ---- K2: per-group centroid + conservative radius ----
__global__ void k_groups(int ngrp_total) {
    const int g = blockIdx.x * blockDim.x + threadIdx.x;
    if (g >= ngrp_total) return;
    const float4* p = g_spts + g * GSZ;
    float cx = 0.f, cy = 0.f, cz = 0.f;
    #pragma unroll
    for (int k = 0; k < GSZ; k++) { cx += p[k].x; cy += p[k].y; cz += p[k].z; }
    cx *= (1.0f / GSZ); cy *= (1.0f / GSZ); cz *= (1.0f / GSZ);
    float m2 = 0.f;
    #pragma unroll
    for (int k = 0; k < GSZ; k++) {
        const float dx = p[k].x - cx, dy = p[k].y - cy, dz = p[k].z - cz;
        m2 = fmaxf(m2, dx * dx + dy * dy + dz * dz);
    }
    const float rg  = sqrtf(m2) * 1.0001f + 1e-5f;   // pad: swallow sqrt rounding
    const float thr = 2.0f + rg;                     // skip exact iff d(i,c) >= 2+rg
    g_grp[g] = make_float4(cx, cy, cz, thr * thr);
}

// ---- K3: main, group-culled pair loop + fused last-block reduction ----
__global__ __launch_bounds__(TILE_I)
void k_main(float* __restrict__ out) {
    __shared__ __align__(16) float4 sj[JS];     // 16KB: this split's sorted points
    __shared__ __align__(16) float4 sg[GPS];    // 1KB: this split's group bounds
    __shared__ int s_ticket;

    const int bidx  = blockIdx.x;
    const int split = bidx % NSPLIT;
    const int itile = (bidx / NSPLIT) % (NN / TILE_I);
    const int b     = bidx / (NSPLIT * (NN / TILE_I));
    const int group = b * (NN / TILE_I) + itile;
    const int tid   = threadIdx.x;

    const int jbase = b * NN + split * JS;
    #pragma unroll
    for (int k = 0; k < JS / TILE_I; k++)
        sj[tid + k * TILE_I] = g_spts[jbase + tid + k * TILE_I];
    if (tid < GPS)
        sg[tid] = g_grp[b * NGRP + split * GPS + tid];
    __syncthreads();

    const int is = itile * TILE_I + tid;          // sorted index within batch
    const float4 q = g_spts[b * NN + is];

    float ax = 0.f, ay = 0.f, az = 0.f;

    for (int g = 0; g < GPS; g++) {
        const float4 G = sg[g];                   // broadcast LDS.128
        const float gx = q.x - G.x, gy = q.y - G.y, gz = q.z - G.z;
        const float d2c = gx * gx + gy * gy + gz * gz;
        if (d2c < G.w) {                          // exact conservative bound
            const int base = g * GSZ;
            #pragma unroll 4
            for (int jj = 0; jj < GSZ; jj++) {
                const float4 p = sj[base + jj];   // broadcast LDS.128
                const float dx = q.x - p.x, dy = q.y - p.y, dz = q.z - p.z;
                const float d2 = dx * dx + dy * dy + dz * dz;
                if (d2 < 4.0f) {                  // exact: pen>0 requires d<2
                    float d;
                    asm("sqrt.approx.f32 %0, %1;" : "=f"(d) : "f"(d2)); // sqrt(0)==0, diag safe
                    const float pen = fmaxf(fmaxf(1.0f, q.w + p.w) - d, 0.0f);
                    ax = fmaf(pen, fminf(fmaxf(dx, -1.f), 1.f), ax);
                    ay = fmaf(pen, fminf(fmaxf(dy, -1.f), 1.f), ay);
                    az = fmaf(pen, fminf(fmaxf(dz, -1.f), 1.f), az);
                }
            }
        }
    }

    // Publish this split's partial (indexed by sorted position).
    const size_t idx3 = ((size_t)b * NN + is) * 3;
    float* dst = g_part + (size_t)split * BB * NN * 3 + idx3;
    dst[0] = ax; dst[1] = ay; dst[2] = az;

    // Last-block-done reduction (fixed split order -> deterministic given sort).
    __threadfence();
    if (tid == 0) s_ticket = atomicAdd(&g_done[group], 1);
    __syncthreads();
    if (s_ticket == NSPLIT - 1) {
        __threadfence();
        float sx = 0.f, sy = 0.f, sz = 0.f;
        #pragma unroll
        for (int sp = 0; sp < NSPLIT; sp++) {
            const float* p = g_part + (size_t)sp * BB * NN * 3 + idx3;
            sx += p[0]; sy += p[1]; sz += p[2];
        }
        const float kk = 0.1f / (float)NN;
        const int o3 = 3 * g_sidx[b * NN + is];   // scatter to original index
        out[o3]     = fmaf(kk, sx, q.x);
        out[o3 + 1] = fmaf(kk, sy, q.y);
        out[o3 + 2] = fmaf(kk, sz, q.z);
        if (tid == 0) g_done[group] = 0;          // reset for next graph replay
    }
}

extern "C" void kernel_launch(void* const* d_in, const int* in_sizes, int n_in,
                              void* d_out, int out_size) {
    const float* coords = (const float*)d_in[0];
    const float* radii  = (const float*)d_in[1];
    float* out = (float*)d_out;

    int B = in_sizes[1] / NN;   // radii elems = B*N
    if (B < 1) B = 1;
    if (B > BB) B = BB;

    k_sort  <<<B, 1024>>>(coords, radii);
    const int ngrp_total = B * NGRP;
    k_groups<<<(ngrp_total + 255) / 256, 256>>>(ngrp_total);
    const int grid = B * (NN / TILE_I) * NSPLIT;
    k_main  <<<grid, TILE_I>>>(out);
}